// round 16
// baseline (speedup 1.0000x reference)
#include <cuda_runtime.h>
#include <cuda_fp16.h>
#include <cstdint>
#include <math.h>

// ---------------- problem constants ----------------
#define BDIM   4096          // batch rows
#define KDIM   4096          // F + S
#define NGATE  6144          // 3*S
#define SDIM   2048
#define HSIZE  8388608L      // B*S

// ---------------- tile config: fp16-split 3-product, 3 CTAs/SM occupancy probe --------
// X = A0 + A1 (fp16 + fp16 residual), W^T = B0 + B1.
// main:  A0*B0  -> fp32 accumulators (m16n8k16.f32)
// corr:  A1*B0 + A0*B1 -> fp16 accumulators (m16n8k16.f16)
// gate = acc32 + f16tof32(acc16). Dropped term A1*B1 ~ 2^-22.
// STAGES=2 + b-half buffers (6 ntiles live) to fit 3 CTAs/SM (3 warps/SMSP).
#define BM 128
#define BNS 32               // state-cols per CTA; B tile = 3 gates x 32 = 96 rows
#define BNROWS 96
#define BK 32                // 2 k16 slices per chunk
#define KT (KDIM / BK)       // 128 chunks
#define STAGES 2
#define NTHREADS 128

// smem: row stride 80B (64B data + 16 pad), conflict-free ldmatrix/cp.async
#define ROWB 80
#define A_T (BM * ROWB)                   // 10240 per A tile
#define B_T (BNROWS * ROWB)               // 7680 per B tile
#define STAGE_BYTES (2 * A_T + 2 * B_T)   // 35840
#define SMEM_TOTAL (STAGES * STAGE_BYTES) // 71680 (x3 CTAs = 215KB/SM)

// ---------------- scratch (no cudaMalloc allowed) ----------------
__device__ __half g_A0[(long)BDIM * KDIM];    // 32MB  fp16(X)
__device__ __half g_A1[(long)BDIM * KDIM];    // 32MB  fp16(X - A0)
__device__ __half g_B0[(long)NGATE * KDIM];   // 50MB  fp16(W^T)
__device__ __half g_B1[(long)NGATE * KDIM];   // 50MB  fp16(W^T - B0)

// ---------------- helpers ----------------
__device__ __forceinline__ uint32_t smem_u32(const void* p) {
    uint32_t a;
    asm("{ .reg .u64 t; cvta.to.shared.u64 t, %1; cvt.u32.u64 %0, t; }" : "=r"(a) : "l"(p));
    return a;
}
__device__ __forceinline__ void cp16(uint32_t dst, const void* src) {
    asm volatile("cp.async.cg.shared.global [%0], [%1], 16;" :: "r"(dst), "l"(src) : "memory");
}
__device__ __forceinline__ void cp_commit() {
    asm volatile("cp.async.commit_group;" ::: "memory");
}
template <int N>
__device__ __forceinline__ void cp_wait() {
    asm volatile("cp.async.wait_group %0;" :: "n"(N) : "memory");
}
__device__ __forceinline__ void ldsm4(uint32_t& r0, uint32_t& r1, uint32_t& r2, uint32_t& r3,
                                      uint32_t addr) {
    asm volatile("ldmatrix.sync.aligned.m8n8.x4.shared.b16 {%0,%1,%2,%3}, [%4];"
                 : "=r"(r0), "=r"(r1), "=r"(r2), "=r"(r3) : "r"(addr));
}
__device__ __forceinline__ void mma_f32acc(float* c, const uint32_t* a, const uint32_t* b) {
    asm volatile(
        "mma.sync.aligned.m16n8k16.row.col.f32.f16.f16.f32 "
        "{%0,%1,%2,%3}, {%4,%5,%6,%7}, {%8,%9}, {%0,%1,%2,%3};"
        : "+f"(c[0]), "+f"(c[1]), "+f"(c[2]), "+f"(c[3])
        : "r"(a[0]), "r"(a[1]), "r"(a[2]), "r"(a[3]), "r"(b[0]), "r"(b[1]));
}
__device__ __forceinline__ void mma_f16acc(uint32_t* c, const uint32_t* a, const uint32_t* b) {
    asm volatile(
        "mma.sync.aligned.m16n8k16.row.col.f16.f16.f16.f16 "
        "{%0,%1}, {%2,%3,%4,%5}, {%6,%7}, {%0,%1};"
        : "+r"(c[0]), "+r"(c[1])
        : "r"(a[0]), "r"(a[1]), "r"(a[2]), "r"(a[3]), "r"(b[0]), "r"(b[1]));
}
__device__ __forceinline__ void split2h(float x, __half& h0, __half& h1) {
    h0 = __float2half_rn(x);
    h1 = __float2half_rn(x - __half2float(h0));
}

// ---------------- prologue: pack & split X (2 independent units/thread, MLP 4) --------
__global__ void pack_split_x(const float* __restrict__ old_h, const float* __restrict__ input,
                             __half* __restrict__ A0, __half* __restrict__ A1) {
    long i0 = (long)blockIdx.x * blockDim.x + threadIdx.x;   // 0 .. 1048575
#pragma unroll
    for (int u = 0; u < 2; u++) {
        long i = i0 + (long)u * 1048576;     // float8 units, 4096*512 total
        int m = (int)(i >> 9);
        int kq = (int)(i & 511);
        const float4* src = (kq < 256)
            ? &reinterpret_cast<const float4*>(old_h)[(long)m * 512 + 2 * kq]
            : &reinterpret_cast<const float4*>(input)[(long)m * 512 + 2 * (kq - 256)];
        float4 v0 = src[0], v1 = src[1];
        __half h0[8], h1[8];
        split2h(v0.x, h0[0], h1[0]); split2h(v0.y, h0[1], h1[1]);
        split2h(v0.z, h0[2], h1[2]); split2h(v0.w, h0[3], h1[3]);
        split2h(v1.x, h0[4], h1[4]); split2h(v1.y, h0[5], h1[5]);
        split2h(v1.z, h0[6], h1[6]); split2h(v1.w, h0[7], h1[7]);
        *reinterpret_cast<uint4*>(&A0[8 * i]) = *reinterpret_cast<uint4*>(h0);
        *reinterpret_cast<uint4*>(&A1[8 * i]) = *reinterpret_cast<uint4*>(h1);
    }
}

// ---------------- prologue: transpose & split W (2 k-tiles/block) ----------------
__global__ void split_w_kernel(const float* __restrict__ W,
                               __half* __restrict__ B0, __half* __restrict__ B1) {
    __shared__ float tile[2][32][33];
    int n0 = blockIdx.x * 32, k0 = blockIdx.y * 64;
    int tid = threadIdx.x;   // 128 threads
#pragma unroll
    for (int e = 0; e < 8; e++) {
        int idx = tid + e * 128;
        int kr = idx >> 5, nc = idx & 31;
        tile[0][kr][nc] = W[(long)(k0 + kr) * NGATE + n0 + nc];
        tile[1][kr][nc] = W[(long)(k0 + 32 + kr) * NGATE + n0 + nc];
    }
    __syncthreads();
    int n = tid >> 2, ko = (tid & 3) * 8;
#pragma unroll
    for (int b = 0; b < 2; b++) {
        __half h0[8], h1[8];
#pragma unroll
        for (int j = 0; j < 8; j++)
            split2h(tile[b][ko + j][n], h0[j], h1[j]);
        long off = (long)(n0 + n) * KDIM + k0 + b * 32 + ko;
        *reinterpret_cast<uint4*>(&B0[off]) = *reinterpret_cast<uint4*>(h0);
        *reinterpret_cast<uint4*>(&B1[off]) = *reinterpret_cast<uint4*>(h1);
    }
}

// ---------------- fused GEMM + LLTM epilogue ----------------
// CTA: 128 rows x 32 state-cols x 3 gates. 4 warps 4(m)x1(n), warp tile 32x96.
// 3 CTAs/SM (3 warps/SMSP) to fill the tensor-pipe gaps at chunk boundaries.
__global__ void __launch_bounds__(NTHREADS, 3) lltm_fused_kernel(
    const float* __restrict__ bias, const float* __restrict__ old_c,
    float* __restrict__ out) {
    extern __shared__ char smem[];
    const uint32_t sbase = smem_u32(smem);

    const int tid = threadIdx.x;
    const int warp = tid >> 5, lane = tid & 31;
    const int g = lane >> 2, t4 = lane & 3;
    const long m0 = (long)blockIdx.x * BM;
    const int n0s = blockIdx.y * BNS;        // state-column base (0..2047)

    float acc[2][12][4];
    uint32_t acch[2][12][2];
#pragma unroll
    for (int i = 0; i < 2; i++)
#pragma unroll
        for (int j = 0; j < 12; j++) {
#pragma unroll
            for (int r = 0; r < 4; r++) acc[i][j][r] = 0.0f;
            acch[i][j][0] = 0u;
            acch[i][j][1] = 0u;
        }

    const uint32_t a_off = (uint32_t)(warp * 32 + (lane & 15)) * ROWB + ((lane >> 4) << 4);
    const uint32_t b_off =
        (uint32_t)((lane & 7) + ((lane >> 4) << 3)) * ROWB + (((lane >> 3) & 1) << 4);

    auto issue_stage = [&](int t) {
        int slot = t & 1;
        long kk = (long)t * BK;
        uint32_t sA0 = sbase + slot * STAGE_BYTES;
        uint32_t sA1 = sA0 + A_T;
        uint32_t sB0 = sA1 + A_T;
        uint32_t sB1 = sB0 + B_T;
#pragma unroll
        for (int i = 0; i < 4; i++) {
            int q = tid + i * NTHREADS;
            int row = q >> 2, cw = q & 3;
            long goff = (m0 + row) * KDIM + kk + cw * 8;
            cp16(sA0 + row * ROWB + cw * 16, g_A0 + goff);
            cp16(sA1 + row * ROWB + cw * 16, g_A1 + goff);
        }
#pragma unroll
        for (int i = 0; i < 3; i++) {
            int q = tid + i * NTHREADS;
            int row = q >> 2, cw = q & 3;        // row 0..95
            long grow = (long)(row >> 5) * SDIM + n0s + (row & 31);
            long goff = grow * KDIM + kk + cw * 8;
            cp16(sB0 + row * ROWB + cw * 16, g_B0 + goff);
            cp16(sB1 + row * ROWB + cw * 16, g_B1 + goff);
        }
    };

    issue_stage(0);
    cp_commit();

    for (int t = 0; t < KT; t++) {
        cp_wait<0>();
        __syncthreads();

        if (t + 1 < KT) issue_stage(t + 1);
        cp_commit();

        uint32_t sA0 = sbase + (t & 1) * STAGE_BYTES;
        uint32_t sA1 = sA0 + A_T;
        uint32_t sB0 = sA1 + A_T;
        uint32_t sB1 = sB0 + B_T;

#pragma unroll
        for (int s = 0; s < 2; s++) {            // 2 k16 slices per chunk
            const uint32_t ks = (uint32_t)s * 32;
            uint32_t a0[2][4], a1[2][4];
#pragma unroll
            for (int i = 0; i < 2; i++) {
                ldsm4(a0[i][0], a0[i][1], a0[i][2], a0[i][3],
                      sA0 + a_off + (uint32_t)i * (16 * ROWB) + ks);
                ldsm4(a1[i][0], a1[i][1], a1[i][2], a1[i][3],
                      sA1 + a_off + (uint32_t)i * (16 * ROWB) + ks);
            }
            // process B in two 6-ntile halves to keep only 12 b-regs live (3 CTA fit)
#pragma unroll
            for (int half = 0; half < 2; half++) {
                uint32_t b[6][2];
#pragma unroll
                for (int jj = 0; jj < 3; jj++)
                    ldsm4(b[2 * jj][0], b[2 * jj][1], b[2 * jj + 1][0], b[2 * jj + 1][1],
                          sB0 + b_off + (uint32_t)(jj + 3 * half) * (16 * ROWB) + ks);
#pragma unroll
                for (int i = 0; i < 2; i++)
#pragma unroll
                    for (int jl = 0; jl < 6; jl++)
                        mma_f32acc(acc[i][6 * half + jl], a0[i], b[jl]);
#pragma unroll
                for (int i = 0; i < 2; i++)
#pragma unroll
                    for (int jl = 0; jl < 6; jl++)
                        mma_f16acc(acch[i][6 * half + jl], a1[i], b[jl]);
#pragma unroll
                for (int jj = 0; jj < 3; jj++)
                    ldsm4(b[2 * jj][0], b[2 * jj][1], b[2 * jj + 1][0], b[2 * jj + 1][1],
                          sB1 + b_off + (uint32_t)(jj + 3 * half) * (16 * ROWB) + ks);
#pragma unroll
                for (int i = 0; i < 2; i++)
#pragma unroll
                    for (int jl = 0; jl < 6; jl++)
                        mma_f16acc(acch[i][6 * half + jl], a0[i], b[jl]);
            }
        }
    }

    // ---- fused LLTM epilogue: gate = acc32 + f16tof32(acc16), fast-math transcend. ----
#pragma unroll
    for (int i = 0; i < 2; i++) {
        long row0 = m0 + warp * 32 + i * 16 + g;
#pragma unroll
        for (int sj = 0; sj < 4; sj++) {
            int col = n0s + sj * 8 + 2 * t4;
            float2 bi = *reinterpret_cast<const float2*>(&bias[col]);
            float2 bo = *reinterpret_cast<const float2*>(&bias[SDIM + col]);
            float2 bc = *reinterpret_cast<const float2*>(&bias[2 * SDIM + col]);
            const float* ai = acc[i][sj];
            const float* ao = acc[i][sj + 4];
            const float* ac = acc[i][sj + 8];
            const uint32_t* hi_ = acch[i][sj];
            const uint32_t* ho_ = acch[i][sj + 4];
            const uint32_t* hc_ = acch[i][sj + 8];
#pragma unroll
            for (int h = 0; h < 2; h++) {        // h=0: row0, h=1: row0+8
                long row = row0 + 8 * h;
                float2 ci = __half22float2(*reinterpret_cast<const __half2*>(&hi_[h]));
                float2 co = __half22float2(*reinterpret_cast<const __half2*>(&ho_[h]));
                float2 cc2 = __half22float2(*reinterpret_cast<const __half2*>(&hc_[h]));
                float2 oc = *reinterpret_cast<const float2*>(&old_c[row * SDIM + col]);
                float2 nh, ncell;
#define LANE(f, idx)                                                    \
                {                                                       \
                    float vi = ai[2 * h + idx] + ci.f + bi.f;           \
                    float vo = ao[2 * h + idx] + co.f + bo.f;           \
                    float vc = ac[2 * h + idx] + cc2.f + bc.f;          \
                    float ig = 1.0f / (1.0f + __expf(-vi));             \
                    float og = 1.0f / (1.0f + __expf(-vo));             \
                    float cel = (vc > 0.0f) ? vc : (__expf(vc) - 1.0f); \
                    float cell = oc.f + cel * ig;                       \
                    ncell.f = cell;                                     \
                    nh.f = tanhf(cell) * og;                            \
                }
                LANE(x, 0) LANE(y, 1)
#undef LANE
                *reinterpret_cast<float2*>(&out[row * SDIM + col]) = nh;
                *reinterpret_cast<float2*>(&out[HSIZE + row * SDIM + col]) = ncell;
            }
        }
    }
}

// ---------------- host ----------------
extern "C" void kernel_launch(void* const* d_in, const int* in_sizes, int n_in,
                              void* d_out, int out_size) {
    const float* W     = (const float*)d_in[0];   // (4096, 6144)
    const float* bias  = (const float*)d_in[1];   // (6144,)
    const float* input = (const float*)d_in[2];   // (4096, 2048)
    const float* old_h = (const float*)d_in[3];   // (4096, 2048)
    const float* old_c = (const float*)d_in[4];   // (4096, 2048)
    float* out = (float*)d_out;                   // [new_h | new_cell]

    void *pA0, *pA1, *pB0, *pB1;
    cudaGetSymbolAddress(&pA0, g_A0);
    cudaGetSymbolAddress(&pA1, g_A1);
    cudaGetSymbolAddress(&pB0, g_B0);
    cudaGetSymbolAddress(&pB1, g_B1);

    pack_split_x<<<4096, 256>>>(old_h, input, (__half*)pA0, (__half*)pA1);
    split_w_kernel<<<dim3(NGATE / 32, KDIM / 64), 128>>>(W, (__half*)pB0, (__half*)pB1);

    cudaFuncSetAttribute(lltm_fused_kernel, cudaFuncAttributeMaxDynamicSharedMemorySize,
                         SMEM_TOTAL);
    lltm_fused_kernel<<<dim3(BDIM / BM, SDIM / BNS), NTHREADS, SMEM_TOTAL>>>(bias, old_c, out);
}

// round 17
// speedup vs baseline: 1.1475x; 1.1475x over previous
#include <cuda_runtime.h>
#include <cuda_fp16.h>
#include <cstdint>
#include <math.h>

// ---------------- problem constants ----------------
#define BDIM   4096          // batch rows
#define KDIM   4096          // F + S
#define NGATE  6144          // 3*S
#define SDIM   2048
#define HSIZE  8388608L      // B*S

// ---------------- tile config: fp16-split 3-product scheme (measured optimum, R12) ----
// X = A0 + A1 (fp16 + fp16 residual), W^T = B0 + B1.
// main:  A0*B0  -> fp32 accumulators (m16n8k16.f32)
// corr:  A1*B0 + A0*B1 -> fp16 accumulators (m16n8k16.f16)
// gate = acc32 + f16tof32(acc16). Dropped term A1*B1 ~ 2^-22.
// Mainloop is at the sm_103 legacy-HMMA practical wall for this structure
// (all faster-dtype paths measured crippled; all occupancy/staging variants slower).
#define BM 128
#define BNS 32               // state-cols per CTA; B tile = 3 gates x 32 = 96 rows
#define BNROWS 96
#define BK 32                // 2 k16 slices per chunk
#define KT (KDIM / BK)       // 128 chunks
#define STAGES 3
#define NTHREADS 128

// smem: row stride 80B (64B data + 16 pad), conflict-free ldmatrix/cp.async
#define ROWB 80
#define A_T (BM * ROWB)                   // 10240 per A tile
#define B_T (BNROWS * ROWB)               // 7680 per B tile
#define STAGE_BYTES (2 * A_T + 2 * B_T)   // 35840
#define SMEM_TOTAL (STAGES * STAGE_BYTES) // 107520 (x2 CTAs = 215KB/SM)

// ---------------- scratch (no cudaMalloc allowed) ----------------
__device__ __half g_A0[(long)BDIM * KDIM];    // 32MB  fp16(X)
__device__ __half g_A1[(long)BDIM * KDIM];    // 32MB  fp16(X - A0)
__device__ __half g_B0[(long)NGATE * KDIM];   // 50MB  fp16(W^T)
__device__ __half g_B1[(long)NGATE * KDIM];   // 50MB  fp16(W^T - B0)

// ---------------- helpers ----------------
__device__ __forceinline__ uint32_t smem_u32(const void* p) {
    uint32_t a;
    asm("{ .reg .u64 t; cvta.to.shared.u64 t, %1; cvt.u32.u64 %0, t; }" : "=r"(a) : "l"(p));
    return a;
}
__device__ __forceinline__ void cp16(uint32_t dst, const void* src) {
    asm volatile("cp.async.cg.shared.global [%0], [%1], 16;" :: "r"(dst), "l"(src) : "memory");
}
__device__ __forceinline__ void cp_commit() {
    asm volatile("cp.async.commit_group;" ::: "memory");
}
template <int N>
__device__ __forceinline__ void cp_wait() {
    asm volatile("cp.async.wait_group %0;" :: "n"(N) : "memory");
}
__device__ __forceinline__ void ldsm4(uint32_t& r0, uint32_t& r1, uint32_t& r2, uint32_t& r3,
                                      uint32_t addr) {
    asm volatile("ldmatrix.sync.aligned.m8n8.x4.shared.b16 {%0,%1,%2,%3}, [%4];"
                 : "=r"(r0), "=r"(r1), "=r"(r2), "=r"(r3) : "r"(addr));
}
__device__ __forceinline__ void mma_f32acc(float* c, const uint32_t* a, const uint32_t* b) {
    asm volatile(
        "mma.sync.aligned.m16n8k16.row.col.f32.f16.f16.f32 "
        "{%0,%1,%2,%3}, {%4,%5,%6,%7}, {%8,%9}, {%0,%1,%2,%3};"
        : "+f"(c[0]), "+f"(c[1]), "+f"(c[2]), "+f"(c[3])
        : "r"(a[0]), "r"(a[1]), "r"(a[2]), "r"(a[3]), "r"(b[0]), "r"(b[1]));
}
__device__ __forceinline__ void mma_f16acc(uint32_t* c, const uint32_t* a, const uint32_t* b) {
    asm volatile(
        "mma.sync.aligned.m16n8k16.row.col.f16.f16.f16.f16 "
        "{%0,%1}, {%2,%3,%4,%5}, {%6,%7}, {%0,%1};"
        : "+r"(c[0]), "+r"(c[1])
        : "r"(a[0]), "r"(a[1]), "r"(a[2]), "r"(a[3]), "r"(b[0]), "r"(b[1]));
}
__device__ __forceinline__ void split2h(float x, __half& h0, __half& h1) {
    h0 = __float2half_rn(x);
    h1 = __float2half_rn(x - __half2float(h0));
}

// ---------------- prologue: pack & split X (2 independent units/thread, MLP 4) --------
__global__ void pack_split_x(const float* __restrict__ old_h, const float* __restrict__ input,
                             __half* __restrict__ A0, __half* __restrict__ A1) {
    long i0 = (long)blockIdx.x * blockDim.x + threadIdx.x;   // 0 .. 1048575
#pragma unroll
    for (int u = 0; u < 2; u++) {
        long i = i0 + (long)u * 1048576;     // float8 units, 4096*512 total
        int m = (int)(i >> 9);
        int kq = (int)(i & 511);
        const float4* src = (kq < 256)
            ? &reinterpret_cast<const float4*>(old_h)[(long)m * 512 + 2 * kq]
            : &reinterpret_cast<const float4*>(input)[(long)m * 512 + 2 * (kq - 256)];
        float4 v0 = src[0], v1 = src[1];
        __half h0[8], h1[8];
        split2h(v0.x, h0[0], h1[0]); split2h(v0.y, h0[1], h1[1]);
        split2h(v0.z, h0[2], h1[2]); split2h(v0.w, h0[3], h1[3]);
        split2h(v1.x, h0[4], h1[4]); split2h(v1.y, h0[5], h1[5]);
        split2h(v1.z, h0[6], h1[6]); split2h(v1.w, h0[7], h1[7]);
        *reinterpret_cast<uint4*>(&A0[8 * i]) = *reinterpret_cast<uint4*>(h0);
        *reinterpret_cast<uint4*>(&A1[8 * i]) = *reinterpret_cast<uint4*>(h1);
    }
}

// ---------------- prologue: transpose & split W (2 k-tiles/block, 16 loads in flight) --
__global__ void split_w_kernel(const float* __restrict__ W,
                               __half* __restrict__ B0, __half* __restrict__ B1) {
    __shared__ float tile[2][32][33];
    int n0 = blockIdx.x * 32, k0 = blockIdx.y * 64;
    int tid = threadIdx.x;   // 128 threads
#pragma unroll
    for (int e = 0; e < 8; e++) {
        int idx = tid + e * 128;
        int kr = idx >> 5, nc = idx & 31;
        tile[0][kr][nc] = W[(long)(k0 + kr) * NGATE + n0 + nc];
        tile[1][kr][nc] = W[(long)(k0 + 32 + kr) * NGATE + n0 + nc];
    }
    __syncthreads();
    int n = tid >> 2, ko = (tid & 3) * 8;
#pragma unroll
    for (int b = 0; b < 2; b++) {
        __half h0[8], h1[8];
#pragma unroll
        for (int j = 0; j < 8; j++)
            split2h(tile[b][ko + j][n], h0[j], h1[j]);
        long off = (long)(n0 + n) * KDIM + k0 + b * 32 + ko;
        *reinterpret_cast<uint4*>(&B0[off]) = *reinterpret_cast<uint4*>(h0);
        *reinterpret_cast<uint4*>(&B1[off]) = *reinterpret_cast<uint4*>(h1);
    }
}

// ---------------- fused GEMM + LLTM epilogue ----------------
// CTA: 128 rows x 32 state-cols x 3 gates. 4 warps 4(m)x1(n), warp tile 32x96.
__global__ void __launch_bounds__(NTHREADS, 2) lltm_fused_kernel(
    const float* __restrict__ bias, const float* __restrict__ old_c,
    float* __restrict__ out) {
    extern __shared__ char smem[];
    const uint32_t sbase = smem_u32(smem);

    const int tid = threadIdx.x;
    const int warp = tid >> 5, lane = tid & 31;
    const int g = lane >> 2, t4 = lane & 3;
    const long m0 = (long)blockIdx.x * BM;
    const int n0s = blockIdx.y * BNS;        // state-column base (0..2047)

    float acc[2][12][4];
    uint32_t acch[2][12][2];
#pragma unroll
    for (int i = 0; i < 2; i++)
#pragma unroll
        for (int j = 0; j < 12; j++) {
#pragma unroll
            for (int r = 0; r < 4; r++) acc[i][j][r] = 0.0f;
            acch[i][j][0] = 0u;
            acch[i][j][1] = 0u;
        }

    const uint32_t a_off = (uint32_t)(warp * 32 + (lane & 15)) * ROWB + ((lane >> 4) << 4);
    const uint32_t b_off =
        (uint32_t)((lane & 7) + ((lane >> 4) << 3)) * ROWB + (((lane >> 3) & 1) << 4);

    auto issue_stage = [&](int t) {
        int slot = t % STAGES;
        long kk = (long)t * BK;
        uint32_t sA0 = sbase + slot * STAGE_BYTES;
        uint32_t sA1 = sA0 + A_T;
        uint32_t sB0 = sA1 + A_T;
        uint32_t sB1 = sB0 + B_T;
#pragma unroll
        for (int i = 0; i < 4; i++) {
            int q = tid + i * NTHREADS;
            int row = q >> 2, cw = q & 3;
            long goff = (m0 + row) * KDIM + kk + cw * 8;
            cp16(sA0 + row * ROWB + cw * 16, g_A0 + goff);
            cp16(sA1 + row * ROWB + cw * 16, g_A1 + goff);
        }
#pragma unroll
        for (int i = 0; i < 3; i++) {
            int q = tid + i * NTHREADS;
            int row = q >> 2, cw = q & 3;        // row 0..95
            long grow = (long)(row >> 5) * SDIM + n0s + (row & 31);
            long goff = grow * KDIM + kk + cw * 8;
            cp16(sB0 + row * ROWB + cw * 16, g_B0 + goff);
            cp16(sB1 + row * ROWB + cw * 16, g_B1 + goff);
        }
    };

#pragma unroll
    for (int s = 0; s < STAGES - 1; s++) {
        issue_stage(s);
        cp_commit();
    }

    for (int t = 0; t < KT; t++) {
        cp_wait<STAGES - 2>();
        __syncthreads();

        if (t + STAGES - 1 < KT) issue_stage(t + STAGES - 1);
        cp_commit();

        uint32_t sA0 = sbase + (t % STAGES) * STAGE_BYTES;
        uint32_t sA1 = sA0 + A_T;
        uint32_t sB0 = sA1 + A_T;
        uint32_t sB1 = sB0 + B_T;

#pragma unroll
        for (int s = 0; s < 2; s++) {            // 2 k16 slices per chunk
            const uint32_t ks = (uint32_t)s * 32;
            uint32_t a0[2][4], a1[2][4], b[12][2];
#pragma unroll
            for (int i = 0; i < 2; i++) {
                ldsm4(a0[i][0], a0[i][1], a0[i][2], a0[i][3],
                      sA0 + a_off + (uint32_t)i * (16 * ROWB) + ks);
                ldsm4(a1[i][0], a1[i][1], a1[i][2], a1[i][3],
                      sA1 + a_off + (uint32_t)i * (16 * ROWB) + ks);
            }
            // B0: main (fp32 acc) + correction A1*B0 (fp16 acc)
#pragma unroll
            for (int jj = 0; jj < 6; jj++)
                ldsm4(b[2 * jj][0], b[2 * jj][1], b[2 * jj + 1][0], b[2 * jj + 1][1],
                      sB0 + b_off + (uint32_t)jj * (16 * ROWB) + ks);
#pragma unroll
            for (int i = 0; i < 2; i++)
#pragma unroll
                for (int j = 0; j < 12; j++) mma_f32acc(acc[i][j], a0[i], b[j]);
#pragma unroll
            for (int i = 0; i < 2; i++)
#pragma unroll
                for (int j = 0; j < 12; j++) mma_f16acc(acch[i][j], a1[i], b[j]);
            // B1: correction A0*B1 (fp16 acc), reuse b regs
#pragma unroll
            for (int jj = 0; jj < 6; jj++)
                ldsm4(b[2 * jj][0], b[2 * jj][1], b[2 * jj + 1][0], b[2 * jj + 1][1],
                      sB1 + b_off + (uint32_t)jj * (16 * ROWB) + ks);
#pragma unroll
            for (int i = 0; i < 2; i++)
#pragma unroll
                for (int j = 0; j < 12; j++) mma_f16acc(acch[i][j], a0[i], b[j]);
        }
    }

    // ---- fused LLTM epilogue: gate = acc32 + f16tof32(acc16), fast-math transcend. ----
#pragma unroll
    for (int i = 0; i < 2; i++) {
        long row0 = m0 + warp * 32 + i * 16 + g;
#pragma unroll
        for (int sj = 0; sj < 4; sj++) {
            int col = n0s + sj * 8 + 2 * t4;
            float2 bi = *reinterpret_cast<const float2*>(&bias[col]);
            float2 bo = *reinterpret_cast<const float2*>(&bias[SDIM + col]);
            float2 bc = *reinterpret_cast<const float2*>(&bias[2 * SDIM + col]);
            const float* ai = acc[i][sj];
            const float* ao = acc[i][sj + 4];
            const float* ac = acc[i][sj + 8];
            const uint32_t* hi_ = acch[i][sj];
            const uint32_t* ho_ = acch[i][sj + 4];
            const uint32_t* hc_ = acch[i][sj + 8];
#pragma unroll
            for (int h = 0; h < 2; h++) {        // h=0: row0, h=1: row0+8
                long row = row0 + 8 * h;
                float2 ci = __half22float2(*reinterpret_cast<const __half2*>(&hi_[h]));
                float2 co = __half22float2(*reinterpret_cast<const __half2*>(&ho_[h]));
                float2 cc2 = __half22float2(*reinterpret_cast<const __half2*>(&hc_[h]));
                float2 oc = *reinterpret_cast<const float2*>(&old_c[row * SDIM + col]);
                float2 nh, ncell;
#define LANE(f, idx)                                                    \
                {                                                       \
                    float vi = ai[2 * h + idx] + ci.f + bi.f;           \
                    float vo = ao[2 * h + idx] + co.f + bo.f;           \
                    float vc = ac[2 * h + idx] + cc2.f + bc.f;          \
                    float ig = 1.0f / (1.0f + __expf(-vi));             \
                    float og = 1.0f / (1.0f + __expf(-vo));             \
                    float cel = (vc > 0.0f) ? vc : (__expf(vc) - 1.0f); \
                    float cell = oc.f + cel * ig;                       \
                    ncell.f = cell;                                     \
                    nh.f = tanhf(cell) * og;                            \
                }
                LANE(x, 0) LANE(y, 1)
#undef LANE
                *reinterpret_cast<float2*>(&out[row * SDIM + col]) = nh;
                *reinterpret_cast<float2*>(&out[HSIZE + row * SDIM + col]) = ncell;
            }
        }
    }
}

// ---------------- host ----------------
extern "C" void kernel_launch(void* const* d_in, const int* in_sizes, int n_in,
                              void* d_out, int out_size) {
    const float* W     = (const float*)d_in[0];   // (4096, 6144)
    const float* bias  = (const float*)d_in[1];   // (6144,)
    const float* input = (const float*)d_in[2];   // (4096, 2048)
    const float* old_h = (const float*)d_in[3];   // (4096, 2048)
    const float* old_c = (const float*)d_in[4];   // (4096, 2048)
    float* out = (float*)d_out;                   // [new_h | new_cell]

    void *pA0, *pA1, *pB0, *pB1;
    cudaGetSymbolAddress(&pA0, g_A0);
    cudaGetSymbolAddress(&pA1, g_A1);
    cudaGetSymbolAddress(&pB0, g_B0);
    cudaGetSymbolAddress(&pB1, g_B1);

    pack_split_x<<<4096, 256>>>(old_h, input, (__half*)pA0, (__half*)pA1);
    split_w_kernel<<<dim3(NGATE / 32, KDIM / 64), 128>>>(W, (__half*)pB0, (__half*)pB1);

    cudaFuncSetAttribute(lltm_fused_kernel, cudaFuncAttributeMaxDynamicSharedMemorySize,
                         SMEM_TOTAL);
    lltm_fused_kernel<<<dim3(BDIM / BM, SDIM / BNS), NTHREADS, SMEM_TOTAL>>>(bias, old_c, out);
}